// round 10
// baseline (speedup 1.0000x reference)
#include <cuda_runtime.h>
#include <cuda_fp16.h>
#include <stdint.h>
#include <math.h>

#define Bn 65536
#define Dn 512
#define Rn 64

// smem: GEMM1 chunk: Vhi [64][136]f16 @0 (17408 B), Vlo @17408  -> 34816 B
//       GEMM2 chunk: BmT hi [64][72]f16 @0 (9216 B), lo @9216   -> 18432 B (reuse)
#define SMEM_MAIN 34816

__device__ float g_Vn[Rn * Dn];
__device__ float g_G[Rn * Rn];
__device__ float g_T[Rn * Rn];
__device__ __align__(16) __half gVhi[Rn * Dn];   // [r][d]
__device__ __align__(16) __half gVlo[Rn * Dn];
__device__ __align__(16) __half gB2hi[Dn * Rn];  // [d][j]
__device__ __align__(16) __half gB2lo[Dn * Rn];

__device__ __forceinline__ uint32_t s2u(const void* p) {
    uint32_t a;
    asm("{ .reg .u64 t; cvta.to.shared.u64 t, %1; cvt.u32.u64 %0, t; }" : "=r"(a) : "l"(p));
    return a;
}
__device__ __forceinline__ uint32_t pack_h2(float x, float y) {
    __half2 h = __floats2half2_rn(x, y);
    return *(uint32_t*)&h;
}
__device__ __forceinline__ void mma16816(float* d, const uint32_t* a, uint32_t b0, uint32_t b1) {
    asm volatile(
        "mma.sync.aligned.m16n8k16.row.col.f32.f16.f16.f32 "
        "{%0,%1,%2,%3}, {%4,%5,%6,%7}, {%8,%9}, {%0,%1,%2,%3};"
        : "+f"(d[0]), "+f"(d[1]), "+f"(d[2]), "+f"(d[3])
        : "r"(a[0]), "r"(a[1]), "r"(a[2]), "r"(a[3]), "r"(b0), "r"(b1));
}
__device__ __forceinline__ void ldsm4(uint32_t addr, uint32_t* r) {
    asm volatile("ldmatrix.sync.aligned.m8n8.x4.shared.b16 {%0,%1,%2,%3}, [%4];"
                 : "=r"(r[0]), "=r"(r[1]), "=r"(r[2]), "=r"(r[3]) : "r"(addr));
}
__device__ __forceinline__ void cp16(uint32_t dst, const void* src) {
    asm volatile("cp.async.ca.shared.global [%0], [%1], 16;" :: "r"(dst), "l"(src));
}
#define CP_COMMIT() asm volatile("cp.async.commit_group;" ::: "memory")
#define CP_WAIT0()  asm volatile("cp.async.wait_group 0;" ::: "memory")

// ==================== prep kernels (unchanged math) ====================
__global__ void k_normalize(const float* __restrict__ hp) {
    int r = blockIdx.x, t = threadIdx.x;
    float local = 0.f;
    for (int d = t; d < Dn; d += 128) { float v = hp[d * Rn + r]; local += v * v; }
    __shared__ float red[128];
    red[t] = local; __syncthreads();
    for (int off = 64; off > 0; off >>= 1) { if (t < off) red[t] += red[t + off]; __syncthreads(); }
    float inv = 1.0f / sqrtf(red[0]);
    for (int d = t; d < Dn; d += 128) {
        float v = hp[d * Rn + r] * inv;
        g_Vn[r * Dn + d] = v;
        __half h = __float2half_rn(v);
        gVhi[r * Dn + d] = h;
        gVlo[r * Dn + d] = __float2half_rn(v - __half2float(h));
    }
}

__global__ void k_gram() {
    int i = blockIdx.x, t = threadIdx.x;
    int j = t >> 3, s = t & 7;
    const float* vi = g_Vn + i * Dn + s * 64;
    const float* vj = g_Vn + j * Dn + s * 64;
    float p = 0.f;
#pragma unroll
    for (int q = 0; q < 64; q++) p += vi[q] * vj[q];
    p += __shfl_xor_sync(0xffffffffu, p, 1);
    p += __shfl_xor_sync(0xffffffffu, p, 2);
    p += __shfl_xor_sync(0xffffffffu, p, 4);
    if (s == 0) g_G[i * Rn + j] = p;
}

__global__ void k_T() {
    __shared__ float sT[Rn][Rn];
    int j = threadIdx.x;
    for (int k = 0; k < Rn; k++) sT[j][k] = 0.f;
    __syncthreads();
    if (j == 0) sT[0][0] = 2.f;
    __syncthreads();
    for (int k = 1; k < Rn; k++) {
        float s = 0.f;
        if (j < k) for (int m = j; m < k; m++) s += sT[j][m] * g_G[m * Rn + k];
        __syncthreads();
        if (j < k) sT[j][k] = -2.f * s;
        if (j == k) sT[j][k] = 2.f;
        __syncthreads();
    }
    for (int k = 0; k < Rn; k++) g_T[j * Rn + k] = sT[j][k];
}

__global__ void k_bmsplit() {
    int j = blockIdx.x, d = threadIdx.x;
    __shared__ float tr[Rn];
    if (d < Rn) tr[d] = g_T[j * Rn + d];
    __syncthreads();
    float acc = 0.f;
#pragma unroll
    for (int r = 0; r < Rn; r++) acc += tr[r] * g_Vn[r * Dn + d];
    __half h = __float2half_rn(acc);
    gB2hi[d * Rn + j] = h;
    gB2lo[d * Rn + j] = __float2half_rn(acc - __half2float(h));
}

// ==================== main fused HMMA kernel ====================
// CTA = 128 rows, 8 warps x 16 rows, 34.8 KB smem -> multi-CTA/SM occupancy.
// GEMM1: P = X V^T, K=512 in 4 chunks (V chunk cp.async-staged).
// GEMM2: OUT = X + (-P) Bm, 8 col-chunks (BmT chunk cp.async-staged).
__global__ __launch_bounds__(256) void k_main(const float* __restrict__ X,
                                              float* __restrict__ OUT) {
    extern __shared__ char smem[];
    const uint32_t sb = s2u(smem);

    const int tid = threadIdx.x;
    const int wid = tid >> 5;
    const int lane = tid & 31;
    const int qid = lane >> 2;
    const int qtr = lane & 3;

    const int base_n = ((lane >> 4) & 1) * 8 + (lane & 7);
    const int koff   = ((lane >> 3) & 1) * 8;

    const int r0 = blockIdx.x * 128 + wid * 16 + qid;
    const float* xrow0 = X + (size_t)r0 * Dn;
    const float* xrow1 = xrow0 + 8 * Dn;

    // ---- GEMM1: P[16x64 per warp] = X * V^T ----
    float acc[8][4];
#pragma unroll
    for (int f = 0; f < 8; f++)
#pragma unroll
        for (int q = 0; q < 4; q++) acc[f][q] = 0.f;

    const uint32_t aV = sb + (uint32_t)(base_n * 136 + koff) * 2;  // stride 272 B/row

    for (int kc = 0; kc < 4; kc++) {
        if (kc > 0) __syncthreads();           // buffer reuse guard
        // stage V chunk [64 n][128 k] hi/lo via cp.async (8x16B per thread)
#pragma unroll
        for (int it = 0; it < 4; it++) {
            int i = tid + it * 256;
            int n = i >> 4, seg = i & 15;
            uint32_t dst = sb + (uint32_t)(n * 272 + seg * 16);
            cp16(dst,          gVhi + n * Dn + kc * 128 + seg * 8);
            cp16(dst + 17408u, gVlo + n * Dn + kc * 128 + seg * 8);
        }
        CP_COMMIT();
        CP_WAIT0();
        __syncthreads();

#pragma unroll
        for (int kk = 0; kk < 8; kk++) {
            int c0 = kc * 128 + kk * 16 + qtr * 2;
            float2 x00 = *(const float2*)(xrow0 + c0);
            float2 x10 = *(const float2*)(xrow1 + c0);
            float2 x01 = *(const float2*)(xrow0 + c0 + 8);
            float2 x11 = *(const float2*)(xrow1 + c0 + 8);
            uint32_t a[4];
            a[0] = pack_h2(x00.x, x00.y);
            a[1] = pack_h2(x10.x, x10.y);
            a[2] = pack_h2(x01.x, x01.y);
            a[3] = pack_h2(x11.x, x11.y);
            uint32_t ak = aV + (uint32_t)kk * 32;
#pragma unroll
            for (int ntp = 0; ntp < 4; ntp++) {
                uint32_t bh[4], bl[4];
                ldsm4(ak + ntp * 4352u, bh);
                ldsm4(ak + ntp * 4352u + 17408u, bl);
                mma16816(acc[2 * ntp],     a, bh[0], bh[1]);
                mma16816(acc[2 * ntp],     a, bl[0], bl[1]);
                mma16816(acc[2 * ntp + 1], a, bh[2], bh[3]);
                mma16816(acc[2 * ntp + 1], a, bl[2], bl[3]);
            }
        }
    }

    // ---- P -> negated fp16 A-fragments of GEMM2 ----
    uint32_t Pq[16];
#pragma unroll
    for (int f = 0; f < 8; f++) {
        Pq[2 * f]     = pack_h2(-acc[f][0], -acc[f][1]);
        Pq[2 * f + 1] = pack_h2(-acc[f][2], -acc[f][3]);
    }

    // ---- GEMM2: OUT = X + (-P) * Bm, 8 chunks of 64 cols ----
    float* orow0 = OUT + (size_t)r0 * Dn;
    float* orow1 = orow0 + 8 * Dn;
    const uint32_t aB = sb + (uint32_t)(base_n * 72 + koff) * 2;   // stride 144 B/row

    for (int nc = 0; nc < 8; nc++) {
        __syncthreads();                       // buffer reuse guard
        // stage BmT chunk [64 d][64 j] hi/lo via cp.async (4x16B per thread)
#pragma unroll
        for (int it = 0; it < 2; it++) {
            int i = tid + it * 256;
            int d = i >> 3, seg = i & 7;
            uint32_t dst = sb + (uint32_t)(d * 144 + seg * 16);
            cp16(dst,         gB2hi + (size_t)(nc * 64 + d) * Rn + seg * 8);
            cp16(dst + 9216u, gB2lo + (size_t)(nc * 64 + d) * Rn + seg * 8);
        }
        CP_COMMIT();

        // acc init from X (overlaps the cp.async in flight; mostly L2 hits)
        float acc2[8][4];
        int cb = nc * 64 + qtr * 2;
#pragma unroll
        for (int nt = 0; nt < 8; nt++) {
            float2 t0 = *(const float2*)(xrow0 + cb + nt * 8);
            float2 t1 = *(const float2*)(xrow1 + cb + nt * 8);
            acc2[nt][0] = t0.x; acc2[nt][1] = t0.y;
            acc2[nt][2] = t1.x; acc2[nt][3] = t1.y;
        }
        CP_WAIT0();
        __syncthreads();

#pragma unroll
        for (int kk = 0; kk < 4; kk++) {
            uint32_t ak = aB + (uint32_t)kk * 32;
#pragma unroll
            for (int ntp = 0; ntp < 4; ntp++) {
                uint32_t bh[4], bl[4];
                ldsm4(ak + ntp * 2304u, bh);
                ldsm4(ak + ntp * 2304u + 9216u, bl);
                mma16816(acc2[2 * ntp],     Pq + 4 * kk, bh[0], bh[1]);
                mma16816(acc2[2 * ntp],     Pq + 4 * kk, bl[0], bl[1]);
                mma16816(acc2[2 * ntp + 1], Pq + 4 * kk, bh[2], bh[3]);
                mma16816(acc2[2 * ntp + 1], Pq + 4 * kk, bl[2], bl[3]);
            }
        }
#pragma unroll
        for (int nt = 0; nt < 8; nt++) {
            *(float2*)(orow0 + cb + nt * 8) = make_float2(acc2[nt][0], acc2[nt][1]);
            *(float2*)(orow1 + cb + nt * 8) = make_float2(acc2[nt][2], acc2[nt][3]);
        }
    }
}

extern "C" void kernel_launch(void* const* d_in, const int* in_sizes, int n_in,
                              void* d_out, int out_size) {
    (void)in_sizes; (void)n_in;
    const float* x    = (const float*)d_in[0];
    const float* sldj = (const float*)d_in[1];
    const float* hp   = (const float*)d_in[2];
    float* out = (float*)d_out;

    cudaFuncSetAttribute(k_main, cudaFuncAttributeMaxDynamicSharedMemorySize, SMEM_MAIN);

    k_normalize<<<Rn, 128>>>(hp);
    k_gram<<<Rn, 512>>>();
    k_T<<<1, 64>>>();
    k_bmsplit<<<Rn, 512>>>();
    k_main<<<Bn / 128, 256, SMEM_MAIN>>>(x, out);

    if (out_size >= Bn * Dn + Bn) {
        cudaMemcpyAsync(out + (size_t)Bn * Dn, sldj, Bn * sizeof(float),
                        cudaMemcpyDeviceToDevice);
    }
}

// round 13
// speedup vs baseline: 1.1955x; 1.1955x over previous
#include <cuda_runtime.h>
#include <cuda_fp16.h>
#include <stdint.h>
#include <math.h>

#define Bn 65536
#define Dn 512
#define Rn 64

// smem: phase1: Vhi [64][520]f16 @0 (66560 B), Vlo @66560 -> 133120 B
//       phase2: BmT hi [512][72]f16 @0 (73728 B), lo @73728 -> 147456 B
#define SMEM_MAIN 147456

__device__ float g_Vn[Rn * Dn];       // normalized reflectors [r][d]
__device__ float g_Graw[Rn * Rn];     // raw Gram of unnormalized u
__device__ float g_NI[Rn];            // 1/||u_i||
__device__ float g_T[Rn * Rn];
__device__ __align__(16) __half gVhi[Rn * Dn];   // [r][d]
__device__ __align__(16) __half gVlo[Rn * Dn];
__device__ __align__(16) __half gB2hi[Dn * Rn];  // [d][j]
__device__ __align__(16) __half gB2lo[Dn * Rn];

__device__ __forceinline__ uint32_t s2u(const void* p) {
    uint32_t a;
    asm("{ .reg .u64 t; cvta.to.shared.u64 t, %1; cvt.u32.u64 %0, t; }" : "=r"(a) : "l"(p));
    return a;
}
__device__ __forceinline__ uint32_t pack_h2(float x, float y) {
    __half2 h = __floats2half2_rn(x, y);
    return *(uint32_t*)&h;
}
__device__ __forceinline__ void mma16816(float* d, const uint32_t* a, uint32_t b0, uint32_t b1) {
    asm volatile(
        "mma.sync.aligned.m16n8k16.row.col.f32.f16.f16.f32 "
        "{%0,%1,%2,%3}, {%4,%5,%6,%7}, {%8,%9}, {%0,%1,%2,%3};"
        : "+f"(d[0]), "+f"(d[1]), "+f"(d[2]), "+f"(d[3])
        : "r"(a[0]), "r"(a[1]), "r"(a[2]), "r"(a[3]), "r"(b0), "r"(b1));
}
__device__ __forceinline__ void ldsm4(uint32_t addr, uint32_t* r) {
    asm volatile("ldmatrix.sync.aligned.m8n8.x4.shared.b16 {%0,%1,%2,%3}, [%4];"
                 : "=r"(r[0]), "=r"(r[1]), "=r"(r[2]), "=r"(r[3]) : "r"(addr));
}

// ==================== prep kernel 1: raw Gram + normalize + split ====================
__global__ void k_g1(const float* __restrict__ hp) {
    int i = blockIdx.x, t = threadIdx.x;
    int j = t >> 3, s = t & 7;
    __shared__ float sdot[Rn];

    const float* base = hp + (s * 64) * Rn;
    float p = 0.f;
#pragma unroll
    for (int q = 0; q < 64; q++) p += base[q * Rn + i] * base[q * Rn + j];
    p += __shfl_xor_sync(0xffffffffu, p, 1);
    p += __shfl_xor_sync(0xffffffffu, p, 2);
    p += __shfl_xor_sync(0xffffffffu, p, 4);
    if (s == 0) sdot[j] = p;
    __syncthreads();

    float ninv = rsqrtf(sdot[i]);
    if (t < Rn) g_Graw[i * Rn + t] = sdot[t];
    if (t == 0) g_NI[i] = ninv;

    float v = hp[t * Rn + i] * ninv;        // t = d (0..511)
    g_Vn[i * Dn + t] = v;
    __half h = __float2half_rn(v);
    gVhi[i * Dn + t] = h;
    gVlo[i * Dn + t] = __float2half_rn(v - __half2float(h));
}

// ==================== prep kernel 2: normalize G + T recurrence ====================
__global__ void k_tb() {
    __shared__ float sG[Rn][Rn];
    __shared__ float sT[Rn][Rn];
    __shared__ float sni[Rn];
    int j = threadIdx.x;                    // 64 threads
    sni[j] = g_NI[j];
    __syncthreads();
    float nj = sni[j];
    for (int k = 0; k < Rn; k++) {
        sG[j][k] = g_Graw[j * Rn + k] * nj * sni[k];
        sT[j][k] = 0.f;
    }
    __syncthreads();
    if (j == 0) sT[0][0] = 2.f;
    __syncthreads();
    for (int k = 1; k < Rn; k++) {
        float s = 0.f;
        if (j < k) for (int m = j; m < k; m++) s += sT[j][m] * sG[m][k];
        __syncthreads();
        if (j < k) sT[j][k] = -2.f * s;
        if (j == k) sT[j][k] = 2.f;
        __syncthreads();
    }
    for (int k = 0; k < Rn; k++) g_T[j * Rn + k] = sT[j][k];
}

// ==================== prep kernel 3: Bm = T @ Vn + split + transpose ====================
__global__ void k_bmsplit() {
    int j = blockIdx.x, d = threadIdx.x;
    __shared__ float tr[Rn];
    if (d < Rn) tr[d] = g_T[j * Rn + d];
    __syncthreads();
    float acc = 0.f;
#pragma unroll
    for (int r = 0; r < Rn; r++) acc += tr[r] * g_Vn[r * Dn + d];
    __half h = __float2half_rn(acc);
    gB2hi[d * Rn + j] = h;
    gB2lo[d * Rn + j] = __float2half_rn(acc - __half2float(h));
}

// ==================== main fused HMMA kernel (4th launch -> profiled) ====================
__global__ __launch_bounds__(512, 1) void k_main(const float* __restrict__ X,
                                                 float* __restrict__ OUT) {
    extern __shared__ char smem[];
    const uint32_t sb = s2u(smem);

    const int tid = threadIdx.x;
    const int wid = tid >> 5;
    const int lane = tid & 31;
    const int qid = lane >> 2;
    const int qtr = lane & 3;

    const int base_n = ((lane >> 4) & 1) * 8 + (lane & 7);
    const int koff   = ((lane >> 3) & 1) * 8;

    const int r0 = blockIdx.x * 256 + wid * 16 + qid;
    const float* xrow0 = X + (size_t)r0 * Dn;
    const float* xrow1 = xrow0 + 8 * Dn;

    // ---- stage ALL of V hi/lo, k-permuted within each 16-k group ----
    // half2-unit: dst col c (group g = c>>3, j = c&7) <- src col 8g + 2(j&3) + (j>>2)
    {
        uint32_t* dsthi = (uint32_t*)smem;                 // stride 260 u32 per row
        uint32_t* dstlo = (uint32_t*)(smem + 66560);
        const uint32_t* srchi = (const uint32_t*)gVhi;     // stride 256 u32 per row
        const uint32_t* srclo = (const uint32_t*)gVlo;
#pragma unroll
        for (int it = 0; it < 32; it++) {
            int i = tid + it * 512;
            int n = i >> 8, c = i & 255;
            int jj = c & 7;
            int src = (c & ~7) + ((jj & 3) << 1) + (jj >> 2);
            dsthi[n * 260 + c] = srchi[n * 256 + src];
            dstlo[n * 260 + c] = srclo[n * 256 + src];
        }
    }
    __syncthreads();

    // ---- GEMM1: P[16x64 per warp] = X * V^T, K=512, zero barriers ----
    float acc[8][4];
#pragma unroll
    for (int f = 0; f < 8; f++)
#pragma unroll
        for (int q = 0; q < 4; q++) acc[f][q] = 0.f;

    const uint32_t aV = sb + (uint32_t)(base_n * 520 + koff) * 2;

    // 2-deep prefetch pipeline: float4 covers this thread's 4 k-values per kstep
    float4 nx0 = *(const float4*)(xrow0 + qtr * 4);
    float4 nx1 = *(const float4*)(xrow1 + qtr * 4);

#pragma unroll 4
    for (int kk = 0; kk < 32; kk++) {
        float4 x0 = nx0, x1 = nx1;
        if (kk < 31) {
            int c0 = (kk + 1) * 16 + qtr * 4;
            nx0 = *(const float4*)(xrow0 + c0);
            nx1 = *(const float4*)(xrow1 + c0);
        }
        uint32_t a[4];
        a[0] = pack_h2(x0.x, x0.y);
        a[1] = pack_h2(x1.x, x1.y);
        a[2] = pack_h2(x0.z, x0.w);
        a[3] = pack_h2(x1.z, x1.w);
        uint32_t ak = aV + (uint32_t)kk * 32;
#pragma unroll
        for (int ntp = 0; ntp < 4; ntp++) {
            uint32_t bh[4], bl[4];
            ldsm4(ak + ntp * 16640u, bh);
            ldsm4(ak + ntp * 16640u + 66560u, bl);
            mma16816(acc[2 * ntp],     a, bh[0], bh[1]);
            mma16816(acc[2 * ntp],     a, bl[0], bl[1]);
            mma16816(acc[2 * ntp + 1], a, bh[2], bh[3]);
            mma16816(acc[2 * ntp + 1], a, bl[2], bl[3]);
        }
    }

    // ---- P -> negated fp16 A-fragments of GEMM2 ----
    uint32_t Pq[16];
#pragma unroll
    for (int f = 0; f < 8; f++) {
        Pq[2 * f]     = pack_h2(-acc[f][0], -acc[f][1]);
        Pq[2 * f + 1] = pack_h2(-acc[f][2], -acc[f][3]);
    }

    // ---- restage smem: BmT hi/lo [512 d][72 pad] f16 ----
    __syncthreads();
    {
        __half* dsthi = (__half*)smem;
        __half* dstlo = (__half*)(smem + 73728);
        for (int i = tid; i < 4096; i += 512) {
            int d = i >> 3, seg = i & 7;
            *(uint4*)(dsthi + d * 72 + seg * 8) = *(const uint4*)(gB2hi + d * Rn + seg * 8);
            *(uint4*)(dstlo + d * 72 + seg * 8) = *(const uint4*)(gB2lo + d * Rn + seg * 8);
        }
    }
    __syncthreads();

    // ---- GEMM2: OUT = X + (-P) * Bm, 8 chunks of 64 cols, zero barriers ----
    float* orow0 = OUT + (size_t)r0 * Dn;
    float* orow1 = orow0 + 8 * Dn;
    const uint32_t aB = sb + (uint32_t)(base_n * 72 + koff) * 2;

    for (int nc = 0; nc < 8; nc++) {
        float acc2[8][4];
        int cb = nc * 64 + qtr * 2;
#pragma unroll
        for (int nt = 0; nt < 8; nt++) {
            float2 t0 = *(const float2*)(xrow0 + cb + nt * 8);
            float2 t1 = *(const float2*)(xrow1 + cb + nt * 8);
            acc2[nt][0] = t0.x; acc2[nt][1] = t0.y;
            acc2[nt][2] = t1.x; acc2[nt][3] = t1.y;
        }
        uint32_t an = aB + (uint32_t)nc * 9216;
#pragma unroll
        for (int kk = 0; kk < 4; kk++) {
            uint32_t ak = an + (uint32_t)kk * 32;
#pragma unroll
            for (int ntp = 0; ntp < 4; ntp++) {
                uint32_t bh[4], bl[4];
                ldsm4(ak + ntp * 2304u, bh);
                ldsm4(ak + ntp * 2304u + 73728u, bl);   // FIXED: lo tile lives at +73728
                mma16816(acc2[2 * ntp],     Pq + 4 * kk, bh[0], bh[1]);
                mma16816(acc2[2 * ntp],     Pq + 4 * kk, bl[0], bl[1]);
                mma16816(acc2[2 * ntp + 1], Pq + 4 * kk, bh[2], bh[3]);
                mma16816(acc2[2 * ntp + 1], Pq + 4 * kk, bl[2], bl[3]);
            }
        }
#pragma unroll
        for (int nt = 0; nt < 8; nt++) {
            *(float2*)(orow0 + cb + nt * 8) = make_float2(acc2[nt][0], acc2[nt][1]);
            *(float2*)(orow1 + cb + nt * 8) = make_float2(acc2[nt][2], acc2[nt][3]);
        }
    }
}

extern "C" void kernel_launch(void* const* d_in, const int* in_sizes, int n_in,
                              void* d_out, int out_size) {
    (void)in_sizes; (void)n_in;
    const float* x    = (const float*)d_in[0];
    const float* sldj = (const float*)d_in[1];
    const float* hp   = (const float*)d_in[2];
    float* out = (float*)d_out;

    cudaFuncSetAttribute(k_main, cudaFuncAttributeMaxDynamicSharedMemorySize, SMEM_MAIN);

    k_g1<<<Rn, 512>>>(hp);        // launch 1
    k_tb<<<1, 64>>>();            // launch 2
    k_bmsplit<<<Rn, 512>>>();     // launch 3
    k_main<<<Bn / 256, 512, SMEM_MAIN>>>(x, out);   // launch 4 -> capture slot

    if (out_size >= Bn * Dn + Bn) {
        cudaMemcpyAsync(out + (size_t)Bn * Dn, sldj, Bn * sizeof(float),
                        cudaMemcpyDeviceToDevice);
    }
}

// round 14
// speedup vs baseline: 1.8823x; 1.5746x over previous
#include <cuda_runtime.h>
#include <cuda_fp16.h>
#include <stdint.h>
#include <math.h>

#define Bn 65536
#define Dn 512
#define Rn 64

// smem: phase1: Vhi [64][520]f16 @0 (66560 B), Vlo @66560 -> 133120 B
//       phase2: BmT hi [512][72]f16 @0 (73728 B), lo @73728 -> 147456 B
#define SMEM_MAIN 147456

__device__ float g_Vn[Rn * Dn];       // normalized reflectors [r][d]
__device__ float g_Graw[Rn * Rn];     // raw Gram of unnormalized u
__device__ float g_NI[Rn];            // 1/||u_i||
__device__ __align__(16) __half gVhi[Rn * Dn];   // [r][d]
__device__ __align__(16) __half gVlo[Rn * Dn];
__device__ __align__(16) __half gB2hi[Dn * Rn];  // [dperm][j]
__device__ __align__(16) __half gB2lo[Dn * Rn];

__device__ __forceinline__ uint32_t s2u(const void* p) {
    uint32_t a;
    asm("{ .reg .u64 t; cvta.to.shared.u64 t, %1; cvt.u32.u64 %0, t; }" : "=r"(a) : "l"(p));
    return a;
}
__device__ __forceinline__ uint32_t pack_h2(float x, float y) {
    __half2 h = __floats2half2_rn(x, y);
    return *(uint32_t*)&h;
}
__device__ __forceinline__ void mma16816(float* d, const uint32_t* a, uint32_t b0, uint32_t b1) {
    asm volatile(
        "mma.sync.aligned.m16n8k16.row.col.f32.f16.f16.f32 "
        "{%0,%1,%2,%3}, {%4,%5,%6,%7}, {%8,%9}, {%0,%1,%2,%3};"
        : "+f"(d[0]), "+f"(d[1]), "+f"(d[2]), "+f"(d[3])
        : "r"(a[0]), "r"(a[1]), "r"(a[2]), "r"(a[3]), "r"(b0), "r"(b1));
}
__device__ __forceinline__ void ldsm4(uint32_t addr, uint32_t* r) {
    asm volatile("ldmatrix.sync.aligned.m8n8.x4.shared.b16 {%0,%1,%2,%3}, [%4];"
                 : "=r"(r[0]), "=r"(r[1]), "=r"(r[2]), "=r"(r[3]) : "r"(addr));
}

// ==================== prep kernel 1: raw Gram + normalize + split ====================
__global__ void k_g1(const float* __restrict__ hp) {
    int i = blockIdx.x, t = threadIdx.x;
    int j = t >> 3, s = t & 7;
    __shared__ float sdot[Rn];

    const float* base = hp + (s * 64) * Rn;
    float p = 0.f;
#pragma unroll
    for (int q = 0; q < 64; q++) p += base[q * Rn + i] * base[q * Rn + j];
    p += __shfl_xor_sync(0xffffffffu, p, 1);
    p += __shfl_xor_sync(0xffffffffu, p, 2);
    p += __shfl_xor_sync(0xffffffffu, p, 4);
    if (s == 0) sdot[j] = p;
    __syncthreads();

    float ninv = rsqrtf(sdot[i]);
    if (t < Rn) g_Graw[i * Rn + t] = sdot[t];
    if (t == 0) g_NI[i] = ninv;

    float v = hp[t * Rn + i] * ninv;        // t = d (0..511)
    g_Vn[i * Dn + t] = v;
    __half h = __float2half_rn(v);
    gVhi[i * Dn + t] = h;
    gVlo[i * Dn + t] = __float2half_rn(v - __half2float(h));
}

// ==================== prep kernel 2: back-substitution for Bm ====================
// (I + 2S) Bm = 2 Vn with S = strict upper of G  (equivalent to Bm = T Vn,
// since the T recurrence gives T(I+2S) = 2I). Thread d owns column d of Bm,
// all 64 values register-resident; G broadcast from smem.
// Stores fp16 hi/lo, transposed [d][j], with the epilogue n-permutation on d.
__global__ void k_solve() {
    __shared__ float sG[Rn][Rn + 1];
    __shared__ float sni[Rn];
    int tid = threadIdx.x;                   // 512 threads, thread = d
    if (tid < Rn) sni[tid] = g_NI[tid];
    __syncthreads();
    for (int i = tid; i < Rn * Rn; i += 512) {
        int r = i >> 6, c = i & 63;
        sG[r][c] = g_Graw[i] * sni[r] * sni[c];
    }
    __syncthreads();

    float b[Rn];
#pragma unroll
    for (int m = 0; m < Rn; m++) b[m] = g_Vn[m * Dn + tid];

    b[63] = 2.f * b[63];
#pragma unroll
    for (int k = 62; k >= 0; k--) {
        float s = 0.f;
#pragma unroll
        for (int m = k + 1; m < Rn; m++) s += sG[k][m] * b[m];
        b[k] = 2.f * b[k] - 2.f * s;
    }

    // store transposed with epilogue permutation of d within each 16-group:
    // a = d&15 = 4q+2h+v  ->  pos = 8h+2q+v
    int a = tid & 15;
    int dperm = (tid & ~15) | (((a >> 1) & 1) << 3) | (((a >> 2) & 3) << 1) | (a & 1);
#pragma unroll
    for (int m = 0; m < Rn; m++) {
        __half h = __float2half_rn(b[m]);
        gB2hi[dperm * Rn + m] = h;
        gB2lo[dperm * Rn + m] = __float2half_rn(b[m] - __half2float(h));
    }
}

// ==================== main fused HMMA kernel ====================
__global__ __launch_bounds__(512, 1) void k_main(const float* __restrict__ X,
                                                 float* __restrict__ OUT) {
    extern __shared__ char smem[];
    const uint32_t sb = s2u(smem);

    const int tid = threadIdx.x;
    const int wid = tid >> 5;
    const int lane = tid & 31;
    const int qid = lane >> 2;
    const int qtr = lane & 3;

    const int base_n = ((lane >> 4) & 1) * 8 + (lane & 7);
    const int koff   = ((lane >> 3) & 1) * 8;

    const int r0 = blockIdx.x * 256 + wid * 16 + qid;
    const float* xrow0 = X + (size_t)r0 * Dn;
    const float* xrow1 = xrow0 + 8 * Dn;

    // ---- stage ALL of V hi/lo, k-permuted within each 16-k group ----
    {
        uint32_t* dsthi = (uint32_t*)smem;                 // stride 260 u32 per row
        uint32_t* dstlo = (uint32_t*)(smem + 66560);
        const uint32_t* srchi = (const uint32_t*)gVhi;
        const uint32_t* srclo = (const uint32_t*)gVlo;
#pragma unroll
        for (int it = 0; it < 32; it++) {
            int i = tid + it * 512;
            int n = i >> 8, c = i & 255;
            int jj = c & 7;
            int src = (c & ~7) + ((jj & 3) << 1) + (jj >> 2);
            dsthi[n * 260 + c] = srchi[n * 256 + src];
            dstlo[n * 260 + c] = srclo[n * 256 + src];
        }
    }
    __syncthreads();

    // ---- GEMM1: P[16x64 per warp] = X * V^T, K=512, zero barriers ----
    float acc[8][4];
#pragma unroll
    for (int f = 0; f < 8; f++)
#pragma unroll
        for (int q = 0; q < 4; q++) acc[f][q] = 0.f;

    const uint32_t aV = sb + (uint32_t)(base_n * 520 + koff) * 2;

    float4 nx0 = *(const float4*)(xrow0 + qtr * 4);
    float4 nx1 = *(const float4*)(xrow1 + qtr * 4);

#pragma unroll 4
    for (int kk = 0; kk < 32; kk++) {
        float4 x0 = nx0, x1 = nx1;
        if (kk < 31) {
            int c0 = (kk + 1) * 16 + qtr * 4;
            nx0 = *(const float4*)(xrow0 + c0);
            nx1 = *(const float4*)(xrow1 + c0);
        }
        uint32_t a[4];
        a[0] = pack_h2(x0.x, x0.y);
        a[1] = pack_h2(x1.x, x1.y);
        a[2] = pack_h2(x0.z, x0.w);
        a[3] = pack_h2(x1.z, x1.w);
        uint32_t ak = aV + (uint32_t)kk * 32;
#pragma unroll
        for (int ntp = 0; ntp < 4; ntp++) {
            uint32_t bh[4], bl[4];
            ldsm4(ak + ntp * 16640u, bh);
            ldsm4(ak + ntp * 16640u + 66560u, bl);
            mma16816(acc[2 * ntp],     a, bh[0], bh[1]);
            mma16816(acc[2 * ntp],     a, bl[0], bl[1]);
            mma16816(acc[2 * ntp + 1], a, bh[2], bh[3]);
            mma16816(acc[2 * ntp + 1], a, bl[2], bl[3]);
        }
    }

    // ---- P -> negated fp16 A-fragments of GEMM2 ----
    uint32_t Pq[16];
#pragma unroll
    for (int f = 0; f < 8; f++) {
        Pq[2 * f]     = pack_h2(-acc[f][0], -acc[f][1]);
        Pq[2 * f + 1] = pack_h2(-acc[f][2], -acc[f][3]);
    }

    // ---- restage smem: BmT hi/lo [512 dpos][72 pad] f16 ----
    __syncthreads();
    {
        __half* dsthi = (__half*)smem;
        __half* dstlo = (__half*)(smem + 73728);
        for (int i = tid; i < 4096; i += 512) {
            int d = i >> 3, seg = i & 7;
            *(uint4*)(dsthi + d * 72 + seg * 8) = *(const uint4*)(gB2hi + d * Rn + seg * 8);
            *(uint4*)(dstlo + d * 72 + seg * 8) = *(const uint4*)(gB2lo + d * Rn + seg * 8);
        }
    }
    __syncthreads();

    // ---- GEMM2: OUT = X + (-P) * Bm, 8 chunks of 64 cols, zero barriers ----
    // n-permutation: position tile 2t+h, pos 2q+v  <->  actual col 16t+4q+2h+v
    float* orow0 = OUT + (size_t)r0 * Dn;
    float* orow1 = orow0 + 8 * Dn;
    const uint32_t aB = sb + (uint32_t)(base_n * 72 + koff) * 2;

    for (int nc = 0; nc < 8; nc++) {
        float acc2[8][4];
#pragma unroll
        for (int t4 = 0; t4 < 4; t4++) {
            int cb = nc * 64 + t4 * 16 + qtr * 4;
            float4 f0 = *(const float4*)(xrow0 + cb);
            float4 f1 = *(const float4*)(xrow1 + cb);
            acc2[2 * t4][0] = f0.x;  acc2[2 * t4][1] = f0.y;
            acc2[2 * t4 + 1][0] = f0.z;  acc2[2 * t4 + 1][1] = f0.w;
            acc2[2 * t4][2] = f1.x;  acc2[2 * t4][3] = f1.y;
            acc2[2 * t4 + 1][2] = f1.z;  acc2[2 * t4 + 1][3] = f1.w;
        }
        uint32_t an = aB + (uint32_t)nc * 9216;
#pragma unroll
        for (int kk = 0; kk < 4; kk++) {
            uint32_t ak = an + (uint32_t)kk * 32;
#pragma unroll
            for (int ntp = 0; ntp < 4; ntp++) {
                uint32_t bh[4], bl[4];
                ldsm4(ak + ntp * 2304u, bh);
                ldsm4(ak + ntp * 2304u + 73728u, bl);
                mma16816(acc2[2 * ntp],     Pq + 4 * kk, bh[0], bh[1]);
                mma16816(acc2[2 * ntp],     Pq + 4 * kk, bl[0], bl[1]);
                mma16816(acc2[2 * ntp + 1], Pq + 4 * kk, bh[2], bh[3]);
                mma16816(acc2[2 * ntp + 1], Pq + 4 * kk, bl[2], bl[3]);
            }
        }
#pragma unroll
        for (int t4 = 0; t4 < 4; t4++) {
            int cb = nc * 64 + t4 * 16 + qtr * 4;
            __stcs((float4*)(orow0 + cb),
                   make_float4(acc2[2 * t4][0], acc2[2 * t4][1],
                               acc2[2 * t4 + 1][0], acc2[2 * t4 + 1][1]));
            __stcs((float4*)(orow1 + cb),
                   make_float4(acc2[2 * t4][2], acc2[2 * t4][3],
                               acc2[2 * t4 + 1][2], acc2[2 * t4 + 1][3]));
        }
    }
}

extern "C" void kernel_launch(void* const* d_in, const int* in_sizes, int n_in,
                              void* d_out, int out_size) {
    (void)in_sizes; (void)n_in;
    const float* x    = (const float*)d_in[0];
    const float* sldj = (const float*)d_in[1];
    const float* hp   = (const float*)d_in[2];
    float* out = (float*)d_out;

    cudaFuncSetAttribute(k_main, cudaFuncAttributeMaxDynamicSharedMemorySize, SMEM_MAIN);

    k_g1<<<Rn, 512>>>(hp);
    k_solve<<<1, 512>>>();
    k_main<<<Bn / 256, 512, SMEM_MAIN>>>(x, out);

    if (out_size >= Bn * Dn + Bn) {
        cudaMemcpyAsync(out + (size_t)Bn * Dn, sldj, Bn * sizeof(float),
                        cudaMemcpyDeviceToDevice);
    }
}

// round 16
// speedup vs baseline: 1.9201x; 1.0200x over previous
#include <cuda_runtime.h>
#include <cuda_fp16.h>
#include <stdint.h>
#include <math.h>

#define Bn 65536
#define Dn 512
#define Rn 64

// smem: phase1: V k-half: hi [64 rows][132 u32] @0 (33792 B), lo @33792 -> 67584 B
//       phase2: BmT d-half: hi [256][36 u32] @0 (36864 B), lo @36864   -> 73728 B
#define SMEM_MAIN 73728

__device__ float g_Vn[Rn * Dn];       // normalized reflectors [r][d]
__device__ float g_Graw[Rn * Rn];     // raw Gram of unnormalized u
__device__ float g_NI[Rn];            // 1/||u_i||
__device__ __align__(16) __half gVhi[Rn * Dn];   // [r][d]
__device__ __align__(16) __half gVlo[Rn * Dn];
__device__ __align__(16) __half gB2hi[Dn * Rn];  // [dperm][j]
__device__ __align__(16) __half gB2lo[Dn * Rn];

__device__ __forceinline__ uint32_t s2u(const void* p) {
    uint32_t a;
    asm("{ .reg .u64 t; cvta.to.shared.u64 t, %1; cvt.u32.u64 %0, t; }" : "=r"(a) : "l"(p));
    return a;
}
__device__ __forceinline__ uint32_t pack_h2(float x, float y) {
    __half2 h = __floats2half2_rn(x, y);
    return *(uint32_t*)&h;
}
__device__ __forceinline__ void mma16816(float* d, const uint32_t* a, uint32_t b0, uint32_t b1) {
    asm volatile(
        "mma.sync.aligned.m16n8k16.row.col.f32.f16.f16.f32 "
        "{%0,%1,%2,%3}, {%4,%5,%6,%7}, {%8,%9}, {%0,%1,%2,%3};"
        : "+f"(d[0]), "+f"(d[1]), "+f"(d[2]), "+f"(d[3])
        : "r"(a[0]), "r"(a[1]), "r"(a[2]), "r"(a[3]), "r"(b0), "r"(b1));
}
__device__ __forceinline__ void ldsm4(uint32_t addr, uint32_t* r) {
    asm volatile("ldmatrix.sync.aligned.m8n8.x4.shared.b16 {%0,%1,%2,%3}, [%4];"
                 : "=r"(r[0]), "=r"(r[1]), "=r"(r[2]), "=r"(r[3]) : "r"(addr));
}

// ==================== prep kernel 1: raw Gram + normalize + split ====================
__global__ void k_g1(const float* __restrict__ hp) {
    int i = blockIdx.x, t = threadIdx.x;
    int j = t >> 3, s = t & 7;
    __shared__ float sdot[Rn];

    const float* base = hp + (s * 64) * Rn;
    float p = 0.f;
#pragma unroll
    for (int q = 0; q < 64; q++) p += base[q * Rn + i] * base[q * Rn + j];
    p += __shfl_xor_sync(0xffffffffu, p, 1);
    p += __shfl_xor_sync(0xffffffffu, p, 2);
    p += __shfl_xor_sync(0xffffffffu, p, 4);
    if (s == 0) sdot[j] = p;
    __syncthreads();

    float ninv = rsqrtf(sdot[i]);
    if (t < Rn) g_Graw[i * Rn + t] = sdot[t];
    if (t == 0) g_NI[i] = ninv;

    float v = hp[t * Rn + i] * ninv;        // t = d (0..511)
    g_Vn[i * Dn + t] = v;
    __half h = __float2half_rn(v);
    gVhi[i * Dn + t] = h;
    gVlo[i * Dn + t] = __float2half_rn(v - __half2float(h));
}

// ==================== prep kernel 2: back-substitution for Bm ====================
// (I + 2S) Bm = 2 Vn, S = strict upper Gram. Thread d owns column d, register-resident.
__global__ void k_solve() {
    __shared__ float sG[Rn][Rn + 1];
    __shared__ float sni[Rn];
    int tid = threadIdx.x;                   // 512 threads, thread = d
    if (tid < Rn) sni[tid] = g_NI[tid];
    __syncthreads();
    for (int i = tid; i < Rn * Rn; i += 512) {
        int r = i >> 6, c = i & 63;
        sG[r][c] = g_Graw[i] * sni[r] * sni[c];
    }
    __syncthreads();

    float b[Rn];
#pragma unroll
    for (int m = 0; m < Rn; m++) b[m] = g_Vn[m * Dn + tid];

    b[63] = 2.f * b[63];
#pragma unroll
    for (int k = 62; k >= 0; k--) {
        float s = 0.f;
#pragma unroll
        for (int m = k + 1; m < Rn; m++) s += sG[k][m] * b[m];
        b[k] = 2.f * b[k] - 2.f * s;
    }

    // store transposed with epilogue permutation of d within each 16-group:
    // a = d&15 = 4q+2h+v  ->  pos = 8h+2q+v
    int a = tid & 15;
    int dperm = (tid & ~15) | (((a >> 1) & 1) << 3) | (((a >> 2) & 3) << 1) | (a & 1);
#pragma unroll
    for (int m = 0; m < Rn; m++) {
        __half h = __float2half_rn(b[m]);
        gB2hi[dperm * Rn + m] = h;
        gB2lo[dperm * Rn + m] = __float2half_rn(b[m] - __half2float(h));
    }
}

// ==================== main fused HMMA kernel ====================
// 256 threads, 8 warps x 32 rows = 256 rows/CTA, 73.7 KB smem -> 2 CTAs/SM.
// Each B ldsm feeds 4 MMAs (M=32 per warp) -> LDSM wavefronts halved.
__global__ __launch_bounds__(256, 2) void k_main(const float* __restrict__ X,
                                                 float* __restrict__ OUT) {
    extern __shared__ char smem[];
    const uint32_t sb = s2u(smem);

    const int tid = threadIdx.x;
    const int wid = tid >> 5;
    const int lane = tid & 31;
    const int qid = lane >> 2;
    const int qtr = lane & 3;

    const int base_n = ((lane >> 4) & 1) * 8 + (lane & 7);
    const int koff   = ((lane >> 3) & 1) * 8;

    const int r0 = blockIdx.x * 256 + wid * 32 + qid;
    const float* xr[4];
    float* orw[4];
#pragma unroll
    for (int m = 0; m < 4; m++) {
        xr[m] = X + (size_t)(r0 + m * 8) * Dn;
        orw[m] = OUT + (size_t)(r0 + m * 8) * Dn;
    }

    float acc[2][8][4];
#pragma unroll
    for (int mt = 0; mt < 2; mt++)
#pragma unroll
        for (int f = 0; f < 8; f++)
#pragma unroll
            for (int q = 0; q < 4; q++) acc[mt][f][q] = 0.f;

    // V tile row stride = 132 u32 = 528 B (16B-aligned per row; banks 4i -> conflict-free)
    const uint32_t aV = sb + (uint32_t)(base_n * 528 + koff * 2);

    // ---- GEMM1: two K-halves of 256, V chunk staged per half ----
    for (int kh = 0; kh < 2; kh++) {
        if (kh > 0) __syncthreads();
        {   // stage V k-half, permuted within each 16-k group (u32 granularity)
            uint32_t* dsthi = (uint32_t*)smem;                // stride 132 u32
            uint32_t* dstlo = (uint32_t*)(smem + 33792);
            const uint32_t* srchi = (const uint32_t*)gVhi;    // stride 256 u32
            const uint32_t* srclo = (const uint32_t*)gVlo;
#pragma unroll
            for (int it = 0; it < 32; it++) {
                int i = tid + it * 256;
                int n = i >> 7, c = i & 127;
                int jj = c & 7;
                int src = (c & ~7) + ((jj & 3) << 1) + (jj >> 2) + kh * 128;
                dsthi[n * 132 + c] = srchi[n * 256 + src];
                dstlo[n * 132 + c] = srclo[n * 256 + src];
            }
        }
        __syncthreads();

        float4 nx0 = *(const float4*)(xr[0] + kh * 256 + qtr * 4);
        float4 nx1 = *(const float4*)(xr[1] + kh * 256 + qtr * 4);
        float4 nx2 = *(const float4*)(xr[2] + kh * 256 + qtr * 4);
        float4 nx3 = *(const float4*)(xr[3] + kh * 256 + qtr * 4);

#pragma unroll 4
        for (int kk = 0; kk < 16; kk++) {
            float4 x0 = nx0, x1 = nx1, x2 = nx2, x3 = nx3;
            if (kk < 15) {
                int c0 = kh * 256 + (kk + 1) * 16 + qtr * 4;
                nx0 = *(const float4*)(xr[0] + c0);
                nx1 = *(const float4*)(xr[1] + c0);
                nx2 = *(const float4*)(xr[2] + c0);
                nx3 = *(const float4*)(xr[3] + c0);
            }
            uint32_t a0[4], a1[4];
            a0[0] = pack_h2(x0.x, x0.y);  a0[1] = pack_h2(x1.x, x1.y);
            a0[2] = pack_h2(x0.z, x0.w);  a0[3] = pack_h2(x1.z, x1.w);
            a1[0] = pack_h2(x2.x, x2.y);  a1[1] = pack_h2(x3.x, x3.y);
            a1[2] = pack_h2(x2.z, x2.w);  a1[3] = pack_h2(x3.z, x3.w);
            uint32_t ak = aV + (uint32_t)kk * 32;
#pragma unroll
            for (int ntp = 0; ntp < 4; ntp++) {
                uint32_t bh[4], bl[4];
                ldsm4(ak + ntp * 8448u, bh);            // 16 rows * 528 B
                ldsm4(ak + ntp * 8448u + 33792u, bl);
                mma16816(acc[0][2 * ntp],     a0, bh[0], bh[1]);
                mma16816(acc[0][2 * ntp],     a0, bl[0], bl[1]);
                mma16816(acc[0][2 * ntp + 1], a0, bh[2], bh[3]);
                mma16816(acc[0][2 * ntp + 1], a0, bl[2], bl[3]);
                mma16816(acc[1][2 * ntp],     a1, bh[0], bh[1]);
                mma16816(acc[1][2 * ntp],     a1, bl[0], bl[1]);
                mma16816(acc[1][2 * ntp + 1], a1, bh[2], bh[3]);
                mma16816(acc[1][2 * ntp + 1], a1, bl[2], bl[3]);
            }
        }
    }

    // ---- P -> negated fp16 A-fragments of GEMM2 ----
    uint32_t Pq[2][16];
#pragma unroll
    for (int mt = 0; mt < 2; mt++)
#pragma unroll
        for (int f = 0; f < 8; f++) {
            Pq[mt][2 * f]     = pack_h2(-acc[mt][f][0], -acc[mt][f][1]);
            Pq[mt][2 * f + 1] = pack_h2(-acc[mt][f][2], -acc[mt][f][3]);
        }

    // ---- GEMM2: OUT = X + (-P) * Bm, two d-halves of 256 cols ----
    const uint32_t aB = sb + (uint32_t)(base_n * 144 + koff * 2);

    for (int dh = 0; dh < 2; dh++) {
        __syncthreads();
        {   // stage BmT d-half [256 dpos][72 halves] hi/lo
            __half* dsthi = (__half*)smem;
            __half* dstlo = (__half*)(smem + 36864);
#pragma unroll
            for (int it = 0; it < 8; it++) {
                int i = tid + it * 256;
                int dl = i >> 3, seg = i & 7;
                size_t gsrc = (size_t)(dh * 256 + dl) * Rn + seg * 8;
                *(uint4*)(dsthi + dl * 72 + seg * 8) = *(const uint4*)(gB2hi + gsrc);
                *(uint4*)(dstlo + dl * 72 + seg * 8) = *(const uint4*)(gB2lo + gsrc);
            }
        }
        __syncthreads();

        for (int ncl = 0; ncl < 8; ncl++) {
            float acc2[2][4][4];
            int cbase = dh * 256 + ncl * 32;
#pragma unroll
            for (int t4 = 0; t4 < 2; t4++) {
                int cb = cbase + t4 * 16 + qtr * 4;
                float4 f0 = *(const float4*)(xr[0] + cb);
                float4 f1 = *(const float4*)(xr[1] + cb);
                float4 f2 = *(const float4*)(xr[2] + cb);
                float4 f3 = *(const float4*)(xr[3] + cb);
                acc2[0][2 * t4][0] = f0.x;     acc2[0][2 * t4][1] = f0.y;
                acc2[0][2 * t4 + 1][0] = f0.z; acc2[0][2 * t4 + 1][1] = f0.w;
                acc2[0][2 * t4][2] = f1.x;     acc2[0][2 * t4][3] = f1.y;
                acc2[0][2 * t4 + 1][2] = f1.z; acc2[0][2 * t4 + 1][3] = f1.w;
                acc2[1][2 * t4][0] = f2.x;     acc2[1][2 * t4][1] = f2.y;
                acc2[1][2 * t4 + 1][0] = f2.z; acc2[1][2 * t4 + 1][1] = f2.w;
                acc2[1][2 * t4][2] = f3.x;     acc2[1][2 * t4][3] = f3.y;
                acc2[1][2 * t4 + 1][2] = f3.z; acc2[1][2 * t4 + 1][3] = f3.w;
            }
            uint32_t an = aB + (uint32_t)ncl * 4608;
#pragma unroll
            for (int kk = 0; kk < 4; kk++) {
                uint32_t ak = an + (uint32_t)kk * 32;
#pragma unroll
                for (int ntp = 0; ntp < 2; ntp++) {
                    uint32_t bh[4], bl[4];
                    ldsm4(ak + ntp * 2304u, bh);
                    ldsm4(ak + ntp * 2304u + 36864u, bl);
                    mma16816(acc2[0][2 * ntp],     Pq[0] + 4 * kk, bh[0], bh[1]);
                    mma16816(acc2[0][2 * ntp],     Pq[0] + 4 * kk, bl[0], bl[1]);
                    mma16816(acc2[0][2 * ntp + 1], Pq[0] + 4 * kk, bh[2], bh[3]);
                    mma16816(acc2[0][2 * ntp + 1], Pq[0] + 4 * kk, bl[2], bl[3]);
                    mma16816(acc2[1][2 * ntp],     Pq[1] + 4 * kk, bh[0], bh[1]);
                    mma16816(acc2[1][2 * ntp],     Pq[1] + 4 * kk, bl[0], bl[1]);
                    mma16816(acc2[1][2 * ntp + 1], Pq[1] + 4 * kk, bh[2], bh[3]);
                    mma16816(acc2[1][2 * ntp + 1], Pq[1] + 4 * kk, bl[2], bl[3]);
                }
            }
#pragma unroll
            for (int t4 = 0; t4 < 2; t4++) {
                int cb = cbase + t4 * 16 + qtr * 4;
                __stcs((float4*)(orw[0] + cb),
                       make_float4(acc2[0][2 * t4][0], acc2[0][2 * t4][1],
                                   acc2[0][2 * t4 + 1][0], acc2[0][2 * t4 + 1][1]));
                __stcs((float4*)(orw[1] + cb),
                       make_float4(acc2[0][2 * t4][2], acc2[0][2 * t4][3],
                                   acc2[0][2 * t4 + 1][2], acc2[0][2 * t4 + 1][3]));
                __stcs((float4*)(orw[2] + cb),
                       make_float4(acc2[1][2 * t4][0], acc2[1][2 * t4][1],
                                   acc2[1][2 * t4 + 1][0], acc2[1][2 * t4 + 1][1]));
                __stcs((float4*)(orw[3] + cb),
                       make_float4(acc2[1][2 * t4][2], acc2[1][2 * t4][3],
                                   acc2[1][2 * t4 + 1][2], acc2[1][2 * t4 + 1][3]));
            }
        }
    }
}

extern "C" void kernel_launch(void* const* d_in, const int* in_sizes, int n_in,
                              void* d_out, int out_size) {
    (void)in_sizes; (void)n_in;
    const float* x    = (const float*)d_in[0];
    const float* sldj = (const float*)d_in[1];
    const float* hp   = (const float*)d_in[2];
    float* out = (float*)d_out;

    cudaFuncSetAttribute(k_main, cudaFuncAttributeMaxDynamicSharedMemorySize, SMEM_MAIN);

    k_g1<<<Rn, 512>>>(hp);
    k_solve<<<1, 512>>>();
    k_main<<<Bn / 256, 256, SMEM_MAIN>>>(x, out);

    if (out_size >= Bn * Dn + Bn) {
        cudaMemcpyAsync(out + (size_t)Bn * Dn, sldj, Bn * sizeof(float),
                        cudaMemcpyDeviceToDevice);
    }
}